// round 5
// baseline (speedup 1.0000x reference)
#include <cuda_runtime.h>
#include <math_constants.h>

// x [B=32, C=256, H=64, W=64] fp32
#define B     32
#define C     256
#define HW    4096
#define W64   64

#define NBB    16                 // b per batch (x-slice 67 MB < 126 MB L2)
#define NBATCH 2

#define THR    128
#define GRID   1184               // 8 CTAs/SM * 148 SMs -> one resident wave

// reduce tiling: per b -> 8 c-ranges x 8 hw-tiles = 64 units
#define HWT    512
#define NHWT   (HW / HWT)         // 8
#define CR     32
#define NCR    (C / CR)           // 8
#define CHUNK  4
#define NCH    (CR / CHUNK)       // 8
#define RED_PER_B 64
#define RED_CTAS  (NBB * RED_PER_B)   // 1024
#define WGT_PER_B 10                  // 2 chw + 8 spatial row-tiles
#define WGT_CTAS  (NBB * WGT_PER_B)   // 160  -> 1024+160 = 1184 = GRID

// ---- scratch ----
__device__ float    g_cpart[B * NHWT * C];
__device__ float4   g_pmax[NCR][B * HW / 4];
__device__ float4   g_psum[NCR][B * HW / 4];
__device__ float    g_chw[B * C];
__device__ float4   g_sp4[B * HW / 4];
__device__ unsigned g_cnt[B];          // per-b reduce arrivals
__device__ unsigned g_arrive;          // global barrier (cumulative per replay)
__device__ unsigned g_depart;          // exit counter for state reset

// smem pool: spatial needs (8+6)*72*2 + 99 = 2115 floats; reduce needs 1024
#define POOL_FLOATS 2200

__device__ __forceinline__ void gbar(int epoch, int tid)
{
    __syncthreads();
    if (tid == 0) {
        __threadfence();
        atomicAdd(&g_arrive, 1u);
        while (*(volatile unsigned*)&g_arrive < (unsigned)(epoch * GRID))
            __nanosleep(64);
        __threadfence();
    }
    __syncthreads();
}

__global__ __launch_bounds__(THR, 8) void kfused(const float* __restrict__ x,
                                                 const float* __restrict__ w1d,
                                                 const float* __restrict__ w2d,
                                                 const float* __restrict__ bias,
                                                 float4* __restrict__ out4)
{
    __shared__ float pool[POOL_FLOATS];
    const int bid  = blockIdx.x;
    const int tid  = threadIdx.x;
    const int warp = tid >> 5;
    const int lane = tid & 31;
    const float4* __restrict__ x4 = (const float4*)x;

    #pragma unroll 1
    for (int bb = 0; bb < NBATCH; ++bb) {
        const int b0 = bb * NBB;

        if (bid < RED_CTAS) {
            // ================= reduce role =================
            const int b  = b0 + (bid >> 6);
            const int cr = (bid >> 3) & 7;
            const int ht = bid & 7;

            float (*sbuf)[CHUNK][THR] = (float (*)[CHUNK][THR])pool;

            const float4* __restrict__ xp =
                x4 + ((long)(b * C + cr * CR) * HW + ht * HWT) / 4 + tid;

            float4 mx = make_float4(-CUDART_INF_F, -CUDART_INF_F, -CUDART_INF_F, -CUDART_INF_F);
            float4 sm = make_float4(0.f, 0.f, 0.f, 0.f);

            float4 p[CHUNK];
            #pragma unroll
            for (int j = 0; j < CHUNK; ++j) p[j] = xp[j * (HW / 4)];

            #pragma unroll 2
            for (int ch = 0; ch < NCH; ++ch) {
                float4 v[CHUNK];
                #pragma unroll
                for (int j = 0; j < CHUNK; ++j) v[j] = p[j];

                float (*sb)[THR] = sbuf[ch & 1];
                #pragma unroll
                for (int j = 0; j < CHUNK; ++j)
                    sb[j][tid] = (v[j].x + v[j].y) + (v[j].z + v[j].w);

                if (ch + 1 < NCH) {
                    #pragma unroll
                    for (int j = 0; j < CHUNK; ++j)
                        p[j] = xp[((ch + 1) * CHUNK + j) * (HW / 4)];
                }

                #pragma unroll
                for (int j = 0; j < CHUNK; ++j) {
                    mx.x = fmaxf(mx.x, v[j].x); mx.y = fmaxf(mx.y, v[j].y);
                    mx.z = fmaxf(mx.z, v[j].z); mx.w = fmaxf(mx.w, v[j].w);
                    sm.x += v[j].x; sm.y += v[j].y; sm.z += v[j].z; sm.w += v[j].w;
                }

                __syncthreads();
                float r = (sb[warp][lane]      + sb[warp][lane + 32])
                        + (sb[warp][lane + 64] + sb[warp][lane + 96]);
                r += __shfl_xor_sync(0xffffffffu, r, 16);
                r += __shfl_xor_sync(0xffffffffu, r, 8);
                r += __shfl_xor_sync(0xffffffffu, r, 4);
                r += __shfl_xor_sync(0xffffffffu, r, 2);
                r += __shfl_xor_sync(0xffffffffu, r, 1);
                if (lane == 0)
                    g_cpart[(b * NHWT + ht) * C + cr * CR + ch * CHUNK + warp] = r;
                __syncthreads();
            }

            const int o = b * (HW / 4) + ht * (HWT / 4) + tid;
            g_pmax[cr][o] = mx;
            g_psum[cr][o] = sm;

            __threadfence();
            __syncthreads();
            if (tid == 0) atomicAdd(&g_cnt[b], 1u);
        } else {
            // ================= weight role =================
            const int w    = bid - RED_CTAS;        // 0..159
            const int b    = b0 + w / WGT_PER_B;
            const int role = w % WGT_PER_B;

            if (tid == 0) {
                while (*(volatile unsigned*)&g_cnt[b] < RED_PER_B) __nanosleep(128);
                __threadfence();
            }
            __syncthreads();

            if (role < 2) {
                // channel weight: mean -> conv1d(5,pad2) -> sigmoid (half each)
                float* mean = pool;                  // 256 floats
                #pragma unroll
                for (int c = tid; c < C; c += THR) {
                    float acc = 0.f;
                    #pragma unroll
                    for (int ht = 0; ht < NHWT; ++ht)
                        acc += g_cpart[(b * NHWT + ht) * C + c];
                    mean[c] = acc * (1.0f / (float)HW);
                }
                __syncthreads();
                const int c = role * 128 + tid;
                float y = 0.f;
                #pragma unroll
                for (int k = 0; k < 5; ++k) {
                    int cc = c - 2 + k;
                    float m = (cc >= 0 && cc < C) ? mean[cc] : 0.f;
                    y += w1d[k] * m;
                }
                g_chw[b * C + c] = 1.0f / (1.0f + expf(-y));
            } else {
                // spatial weight: rows [r0, r0+8)
                const int r0 = (role - 2) * 8;
                float* smax = pool;                  // [14][72]
                float* savg = pool + 14 * 72;
                float* sw   = pool + 2 * 14 * 72;    // 98 taps + bias

                for (int i = tid; i < 14 * 70; i += THR) {
                    int rr = i / 70, cc = i % 70;
                    int gr = r0 - 3 + rr, gc = cc - 3;
                    float mv = 0.f, av = 0.f;
                    if (gr >= 0 && gr < W64 && gc >= 0 && gc < W64) {
                        int gi = b * HW + gr * W64 + gc;
                        mv = -CUDART_INF_F;
                        #pragma unroll
                        for (int r = 0; r < NCR; ++r) {
                            mv = fmaxf(mv, ((const float*)g_pmax[r])[gi]);
                            av += ((const float*)g_psum[r])[gi];
                        }
                        av *= (1.0f / (float)C);
                    }
                    smax[rr * 72 + cc] = mv;
                    savg[rr * 72 + cc] = av;
                }
                if (tid < 98) sw[tid] = w2d[tid];
                if (tid == 0) sw[98] = bias[0];
                __syncthreads();

                float* __restrict__ sp = (float*)g_sp4;
                #pragma unroll
                for (int k = 0; k < 4; ++k) {
                    int oi   = tid + k * THR;        // 0..511
                    int orow = oi >> 6;
                    int ocol = oi & 63;
                    float acc = sw[98];
                    #pragma unroll
                    for (int kh = 0; kh < 7; ++kh) {
                        #pragma unroll
                        for (int kw = 0; kw < 7; ++kw) {
                            acc += sw[kh * 7 + kw]      * smax[(orow + kh) * 72 + ocol + kw];
                            acc += sw[49 + kh * 7 + kw] * savg[(orow + kh) * 72 + ocol + kw];
                        }
                    }
                    sp[b * HW + (r0 + orow) * W64 + ocol] = 1.0f / (1.0f + expf(-acc));
                }
            }
        }

        // ---- all weights for this batch visible ----
        gbar(bb + 1, tid);

        // ================= apply role (all CTAs) =================
        // out = x * (chw + sp + 1); x[b0..b0+16) is L2-hot from reduce.
        const int TOT4 = NBB * C * (HW / 4);           // 4194304
        const int base = b0 * C * (HW / 4);
        for (int i = bid * THR + tid; i < TOT4; i += GRID * THR) {
            const int hw4 = i & 1023;
            const int bc  = i >> 10;                   // b_local*256 + c
            const float  cw = g_chw[b0 * C + bc] + 1.0f;
            const float4 sp = g_sp4[(b0 + (bc >> 8)) * 1024 + hw4];
            const float4 v  = x4[base + i];
            float4 o;
            o.x = v.x * (cw + sp.x);
            o.y = v.y * (cw + sp.y);
            o.z = v.z * (cw + sp.z);
            o.w = v.w * (cw + sp.w);
            __stcs(&out4[base + i], o);
        }
        __syncthreads();
    }

    // ---- reset global state for next graph replay (last CTA out) ----
    if (tid == 0) {
        __threadfence();
        unsigned d = atomicAdd(&g_depart, 1u);
        if (d == GRID - 1) {
            for (int i = 0; i < B; ++i) g_cnt[i] = 0;
            g_arrive = 0;
            __threadfence();
            g_depart = 0;
        }
    }
}

// =====================================================================
extern "C" void kernel_launch(void* const* d_in, const int* in_sizes, int n_in,
                              void* d_out, int out_size)
{
    const float* x    = (const float*)d_in[0];  // [32,256,64,64]
    const float* w1d  = (const float*)d_in[1];  // [1,1,5]
    const float* w2d  = (const float*)d_in[2];  // [1,2,7,7]
    const float* bias = (const float*)d_in[3];  // [1]
    float* out = (float*)d_out;

    kfused<<<GRID, THR>>>(x, w1d, w2d, bias, (float4*)out);
}

// round 6
// speedup vs baseline: 1.0472x; 1.0472x over previous
#include <cuda_runtime.h>
#include <math_constants.h>

// x [B=32, C=256, H=64, W=64] fp32
#define B    32
#define C    256
#define HW   4096
#define W64  64

// ---- k1 tiling (reduce role) ----
#define K1T    128
#define HWT    512
#define NHWT   (HW / HWT)      // 8
#define CR     64
#define NCR    (C / CR)        // 4
#define CHUNK  4
#define NCHUNK (CR / CHUNK)    // 16
#define RED_PER_B  (NCR * NHWT)       // 32 reduce CTAs per b
#define RED_CTAS   (B * RED_PER_B)    // 1024
#define WGT_PER_B  5                  // 1 chw + 4 spatial 16-row tiles
#define WGT_CTAS   (B * WGT_PER_B)    // 160 -> grid 1184 = 8/SM * 148
#define K1_GRID    (RED_CTAS + WGT_CTAS)

// ---- scratch (device globals; allocation-free) ----
__device__ float    g_cpart[B * NHWT * C];
__device__ float4   g_pmax[NCR][B * HW / 4];
__device__ float4   g_psum[NCR][B * HW / 4];
__device__ float    g_chw[B * C];
__device__ float4   g_sp4[B * HW / 4];
__device__ unsigned g_cnt[B];        // per-b reduce-CTA arrivals (reset by k4)

// smem pool: spatial role needs (16+6)*72*2 + 99 = 3267 floats (12.8 KB)
#define POOL_FLOATS 3268

// =====================================================================
// k1: reduce CTAs (bid < 1024) stream x with an 8-deep LDG pipeline and
//     emit per-(b,c) partial sums + per-(b,hw) max/sum partials.
//     Weight CTAs (160, tail of grid) sleep-spin on per-b counters, then
//     compute channel weight (conv1d+sigmoid) / spatial weight (7x7 conv).
//     Grid = 1184 CTAs = exactly one resident wave -> spin is safe.
// =====================================================================
__global__ __launch_bounds__(K1T, 8) void k1_fused(const float* __restrict__ x,
                                                   const float* __restrict__ w1d,
                                                   const float* __restrict__ w2d,
                                                   const float* __restrict__ bias)
{
    __shared__ float pool[POOL_FLOATS];
    const int bid  = blockIdx.x;
    const int tid  = threadIdx.x;
    const int warp = tid >> 5;
    const int lane = tid & 31;

    if (bid < RED_CTAS) {
        // ================= reduce role =================
        const int b  = bid >> 5;            // /32
        const int cr = (bid >> 3) & 3;
        const int ht = bid & 7;

        float (*sbuf)[CHUNK][K1T] = (float (*)[CHUNK][K1T])pool;

        const float4* __restrict__ xp =
            (const float4*)x + ((long)(b * C + cr * CR) * HW + ht * HWT) / 4 + tid;

        float4 mx = make_float4(-CUDART_INF_F, -CUDART_INF_F, -CUDART_INF_F, -CUDART_INF_F);
        float4 sm = make_float4(0.f, 0.f, 0.f, 0.f);

        // two 4-channel chunks in flight -> 8 outstanding LDG.128 per thread
        float4 p0[CHUNK], p1[CHUNK];
        #pragma unroll
        for (int j = 0; j < CHUNK; ++j) p0[j] = xp[j * (HW / 4)];
        #pragma unroll
        for (int j = 0; j < CHUNK; ++j) p1[j] = xp[(CHUNK + j) * (HW / 4)];

        #pragma unroll 2
        for (int ch = 0; ch < NCHUNK; ++ch) {
            float4 v[CHUNK];
            #pragma unroll
            for (int j = 0; j < CHUNK; ++j) v[j] = p0[j];

            float (*sb)[K1T] = sbuf[ch & 1];
            #pragma unroll
            for (int j = 0; j < CHUNK; ++j)
                sb[j][tid] = (v[j].x + v[j].y) + (v[j].z + v[j].w);

            #pragma unroll
            for (int j = 0; j < CHUNK; ++j) p0[j] = p1[j];
            if (ch + 2 < NCHUNK) {
                #pragma unroll
                for (int j = 0; j < CHUNK; ++j)
                    p1[j] = xp[((ch + 2) * CHUNK + j) * (HW / 4)];
            }

            #pragma unroll
            for (int j = 0; j < CHUNK; ++j) {
                mx.x = fmaxf(mx.x, v[j].x); mx.y = fmaxf(mx.y, v[j].y);
                mx.z = fmaxf(mx.z, v[j].z); mx.w = fmaxf(mx.w, v[j].w);
                sm.x += v[j].x; sm.y += v[j].y; sm.z += v[j].z; sm.w += v[j].w;
            }

            __syncthreads();
            float r = (sb[warp][lane]      + sb[warp][lane + 32])
                    + (sb[warp][lane + 64] + sb[warp][lane + 96]);
            r += __shfl_xor_sync(0xffffffffu, r, 16);
            r += __shfl_xor_sync(0xffffffffu, r, 8);
            r += __shfl_xor_sync(0xffffffffu, r, 4);
            r += __shfl_xor_sync(0xffffffffu, r, 2);
            r += __shfl_xor_sync(0xffffffffu, r, 1);
            if (lane == 0)
                g_cpart[(b * NHWT + ht) * C + cr * CR + ch * CHUNK + warp] = r;
        }

        const int o = b * (HW / 4) + ht * (HWT / 4) + tid;
        g_pmax[cr][o] = mx;
        g_psum[cr][o] = sm;

        __threadfence();
        __syncthreads();
        if (tid == 0) atomicAdd(&g_cnt[b], 1u);
    } else {
        // ================= weight role =================
        const int w    = bid - RED_CTAS;       // 0..159
        const int b    = w / WGT_PER_B;
        const int role = w % WGT_PER_B;

        if (tid == 0) {
            while (*(volatile unsigned*)&g_cnt[b] < RED_PER_B) __nanosleep(256);
            __threadfence();
        }
        __syncthreads();

        if (role == 0) {
            // channel weight: mean -> conv1d(5, pad 2) -> sigmoid
            float* mean = pool;                // 256 floats
            #pragma unroll
            for (int c = tid; c < C; c += K1T) {
                float acc = 0.f;
                #pragma unroll
                for (int ht = 0; ht < NHWT; ++ht)
                    acc += g_cpart[(b * NHWT + ht) * C + c];
                mean[c] = acc * (1.0f / (float)HW);
            }
            __syncthreads();
            #pragma unroll
            for (int c = tid; c < C; c += K1T) {
                float y = 0.f;
                #pragma unroll
                for (int k = 0; k < 5; ++k) {
                    int cc = c - 2 + k;
                    float m = (cc >= 0 && cc < C) ? mean[cc] : 0.f;
                    y += w1d[k] * m;
                }
                g_chw[b * C + c] = 1.0f / (1.0f + expf(-y));
            }
        } else {
            // spatial weight tile: rows [r0, r0+16)
            const int r0 = (role - 1) * 16;
            float* smax = pool;                 // [22][72]
            float* savg = pool + 22 * 72;
            float* sw   = pool + 2 * 22 * 72;   // 98 taps + bias at [98]

            for (int i = tid; i < 22 * 70; i += K1T) {
                int rr = i / 70, cc = i % 70;
                int gr = r0 - 3 + rr, gc = cc - 3;
                float mv = 0.f, av = 0.f;
                if (gr >= 0 && gr < W64 && gc >= 0 && gc < W64) {
                    int gi = b * HW + gr * W64 + gc;
                    mv = -CUDART_INF_F;
                    #pragma unroll
                    for (int r = 0; r < NCR; ++r) {
                        mv = fmaxf(mv, ((const float*)g_pmax[r])[gi]);
                        av += ((const float*)g_psum[r])[gi];
                    }
                    av *= (1.0f / (float)C);
                }
                smax[rr * 72 + cc] = mv;
                savg[rr * 72 + cc] = av;
            }
            if (tid < 98) sw[tid] = w2d[tid];
            if (tid == 0) sw[98] = bias[0];
            __syncthreads();

            float* __restrict__ sp = (float*)g_sp4;
            #pragma unroll
            for (int k = 0; k < 8; ++k) {
                int oi   = tid + k * K1T;       // 0..1023
                int orow = oi >> 6;
                int ocol = oi & 63;
                float acc = sw[98];
                #pragma unroll
                for (int kh = 0; kh < 7; ++kh) {
                    #pragma unroll
                    for (int kw = 0; kw < 7; ++kw) {
                        acc += sw[kh * 7 + kw]      * smax[(orow + kh) * 72 + ocol + kw];
                        acc += sw[49 + kh * 7 + kw] * savg[(orow + kh) * 72 + ocol + kw];
                    }
                }
                sp[b * HW + (r0 + orow) * W64 + ocol] = 1.0f / (1.0f + expf(-acc));
            }
        }
    }
}

// =====================================================================
// k4: out = x * (chw[b,c] + sp[b,hw] + 1), reversed traversal + stcs.
//     Also resets the per-b counters for the next graph replay.
// =====================================================================
#define TOTAL4 (B * C * HW / 4)
__global__ __launch_bounds__(256) void k4_scale(const float4* __restrict__ x4,
                                                float4* __restrict__ out4)
{
    if (blockIdx.x == 0 && threadIdx.x < B) g_cnt[threadIdx.x] = 0;

    const int i4  = (TOTAL4 - 1) - (blockIdx.x * 256 + threadIdx.x);
    const int hw4 = i4 & 1023;
    const int bc  = i4 >> 10;
    const int b   = bc >> 8;

    const float  cw = g_chw[bc] + 1.0f;
    const float4 sp = g_sp4[b * 1024 + hw4];
    const float4 v  = x4[i4];

    float4 o;
    o.x = v.x * (cw + sp.x);
    o.y = v.y * (cw + sp.y);
    o.z = v.z * (cw + sp.z);
    o.w = v.w * (cw + sp.w);
    __stcs(&out4[i4], o);
}

// =====================================================================
extern "C" void kernel_launch(void* const* d_in, const int* in_sizes, int n_in,
                              void* d_out, int out_size)
{
    const float* x    = (const float*)d_in[0];  // [32,256,64,64]
    const float* w1d  = (const float*)d_in[1];  // [1,1,5]
    const float* w2d  = (const float*)d_in[2];  // [1,2,7,7]
    const float* bias = (const float*)d_in[3];  // [1]
    float* out = (float*)d_out;

    k1_fused<<<K1_GRID, K1T>>>(x, w1d, w2d, bias);
    k4_scale<<<TOTAL4 / 256, 256>>>((const float4*)x, (float4*)out);
}